// round 14
// baseline (speedup 1.0000x reference)
#include <cuda_runtime.h>
#include <cuda_bf16.h>
#include <cstdint>

#define NN 10000
#define EE 160000
#define CC 128
#define DD 512
#define HH 64
#define W4C 640
#define HT 130   // padded stride for transposed h tiles [k][e]

#define NCH 2
#define EBLK (EE / 128)            // 1250 blocks total
#define CBLK (EBLK / NCH)          // 625 blocks per chunk

#define INV_SQRT3 0.57735026918962576f
#define INV_SQRT2 0.70710678118654752f
#define LIN_SCALE 0.088388347648318447f   // 1/sqrt(128)

// Scratch (device globals: no runtime allocation allowed)
// g_agg layout: [node][channel c (128)][4] where 4 = (m0, m1x, m1y, m1z)
__device__ float g_agg[(size_t)NN * DD];
// A fragments (layer-3 activations), bf16 hi/lo, m16n8k16 A-fragment order:
// uint4 per [blk(1250)][warp(8)][kt(4)][lane(32)]
__device__ uint4 g_ah4[1250 * 8 * 4 * 32];
__device__ uint4 g_al4[1250 * 8 * 4 * 32];
// Wm4 split bf16, B-fragment order, hi+lo packed: uint4{h0,h1,l0,l1}
// per [kt(4)][nt(80)][lane(32)]
__device__ uint4 g_b4[4 * 80 * 32];

typedef unsigned long long u64;

__device__ __forceinline__ u64 pack2(float lo, float hi) {
    u64 r; asm("mov.b64 %0, {%1, %2};" : "=l"(r) : "f"(lo), "f"(hi)); return r;
}
__device__ __forceinline__ void unpack2(u64 v, float& lo, float& hi) {
    asm("mov.b64 {%0, %1}, %2;" : "=f"(lo), "=f"(hi) : "l"(v));
}
__device__ __forceinline__ void fma2(u64& d, u64 a, u64 b) {
    asm("fma.rn.f32x2 %0, %1, %2, %0;" : "+l"(d) : "l"(a), "l"(b));
}
__device__ __forceinline__ float silu_f(float x) { return x / (1.0f + __expf(-x)); }

__device__ __forceinline__ uint32_t pack_bf16(__nv_bfloat16 first, __nv_bfloat16 second) {
    return (uint32_t)__bfloat16_as_ushort(first) | ((uint32_t)__bfloat16_as_ushort(second) << 16);
}
__device__ __forceinline__ void split_pack(float x, float y, uint32_t& hi, uint32_t& lo) {
    const __nv_bfloat16 bx = __float2bfloat16(x);
    const __nv_bfloat16 by = __float2bfloat16(y);
    const __nv_bfloat16 rx = __float2bfloat16(x - __bfloat162float(bx));
    const __nv_bfloat16 ry = __float2bfloat16(y - __bfloat162float(by));
    hi = pack_bf16(bx, by);
    lo = pack_bf16(rx, ry);
}

__device__ __forceinline__ void mma_bf16(float* c, const uint32_t* a, uint32_t b0, uint32_t b1) {
    asm volatile("mma.sync.aligned.m16n8k16.row.col.f32.bf16.bf16.f32 "
        "{%0,%1,%2,%3}, {%4,%5,%6,%7}, {%8,%9}, {%0,%1,%2,%3};"
        : "+f"(c[0]), "+f"(c[1]), "+f"(c[2]), "+f"(c[3])
        : "r"(a[0]), "r"(a[1]), "r"(a[2]), "r"(a[3]), "r"(b0), "r"(b1));
}

// ---------------------------------------------------------------------------
// prep: split Wm4 -> bf16 hi/lo in B-fragment order, hi+lo packed per uint4.
// ---------------------------------------------------------------------------
__global__ void __launch_bounds__(256)
prep_b4_kernel(const float* __restrict__ Wm4)
{
    const int tid = blockIdx.x * 256 + threadIdx.x;
    if (tid >= 4 * 80 * 32) return;
    const int lane = tid & 31;
    const int idx = tid >> 5;           // kt*80 + nt
    const int kt = idx / 80, nt = idx % 80;
    const int g = lane >> 2, t = lane & 3;
    const int n = nt * 8 + g;
    const int k0 = kt * 16 + 2 * t;

    const float v00 = Wm4[(k0)     * W4C + n];
    const float v01 = Wm4[(k0 + 1) * W4C + n];
    const float v10 = Wm4[(k0 + 8) * W4C + n];
    const float v11 = Wm4[(k0 + 9) * W4C + n];
    uint4 o;
    split_pack(v00, v01, o.x, o.z);
    split_pack(v10, v11, o.y, o.w);
    g_b4[idx * 32 + lane] = o;
}

// ---------------------------------------------------------------------------
// One 64->64 layer, register-blocked: 4 columns x 8 edges per thread.
// ---------------------------------------------------------------------------
__device__ __forceinline__ void layer_rb(const float* __restrict__ W,
                                         const float* sIn, float* sOut,
                                         int jbase, int ebase)
{
    u64 acc[4][4];
#pragma unroll
    for (int c = 0; c < 4; ++c)
#pragma unroll
        for (int p = 0; p < 4; ++p) acc[c][p] = 0ull;

#pragma unroll 4
    for (int k = 0; k < HH; ++k) {
        const float4 w4 = __ldg((const float4*)(W + k * HH + jbase));
        const u64* hp = (const u64*)(sIn + k * HT + ebase);
        const u64 h0 = hp[0], h1 = hp[1], h2 = hp[2], h3 = hp[3];
        const float wv[4] = {w4.x, w4.y, w4.z, w4.w};
#pragma unroll
        for (int c = 0; c < 4; ++c) {
            const u64 w2 = pack2(wv[c], wv[c]);
            fma2(acc[c][0], h0, w2);
            fma2(acc[c][1], h1, w2);
            fma2(acc[c][2], h2, w2);
            fma2(acc[c][3], h3, w2);
        }
    }
#pragma unroll
    for (int c = 0; c < 4; ++c) {
        u64* op = (u64*)(sOut + (jbase + c) * HT + ebase);
#pragma unroll
        for (int p = 0; p < 4; ++p) {
            float lo, hi; unpack2(acc[c][p], lo, hi);
            op[p] = pack2(silu_f(lo), silu_f(hi));
        }
    }
}

// ---------------------------------------------------------------------------
// Kernel 1: MLP layers 1-3 (scalar) -> store split bf16 A-fragments (chunked).
// ---------------------------------------------------------------------------
__global__ void __launch_bounds__(256, 2)
mlp_kernel(const float* __restrict__ emb, const float* __restrict__ Wm1,
           const float* __restrict__ Wm2, const float* __restrict__ Wm3,
           int blk0)
{
    extern __shared__ float sm[];
    float* sE  = sm;            // 128 x 8
    float* sW1 = sm + 1024;     // 8 x 64
    float* sHa = sm + 1536;     // [64][130]
    float* sHb = sm + 1536 + HH * HT;

    const int tid = threadIdx.x;
    const int blk = blk0 + blockIdx.x;
    const size_t e0 = (size_t)blk * 128;

    for (int i = tid; i < 1024; i += 256) sE[i] = emb[e0 * 8 + i];
    for (int i = tid; i < 512; i += 256)  sW1[i] = Wm1[i];
    __syncthreads();

    const int jq = tid & 15;
    const int eg = tid >> 4;
    const int jbase = jq * 4;
    const int ebase = eg * 8;

    // layer 1
    {
        float w[8][4];
#pragma unroll
        for (int r = 0; r < 8; ++r) {
            const float4 w4 = *(const float4*)(sW1 + r * HH + jbase);
            w[r][0] = w4.x; w[r][1] = w4.y; w[r][2] = w4.z; w[r][3] = w4.w;
        }
#pragma unroll
        for (int e = 0; e < 8; ++e) {
            const float4 ea = *(const float4*)(sE + (ebase + e) * 8);
            const float4 eb = *(const float4*)(sE + (ebase + e) * 8 + 4);
            const float er[8] = {ea.x, ea.y, ea.z, ea.w, eb.x, eb.y, eb.z, eb.w};
#pragma unroll
            for (int c = 0; c < 4; ++c) {
                float acc = 0.f;
#pragma unroll
                for (int r = 0; r < 8; ++r) acc += er[r] * w[r][c];
                sHa[(jbase + c) * HT + ebase + e] = silu_f(acc);
            }
        }
    }
    __syncthreads();
    layer_rb(Wm2, sHa, sHb, jbase, ebase);
    __syncthreads();
    layer_rb(Wm3, sHb, sHa, jbase, ebase);
    __syncthreads();

    // build + store A fragments (bf16 hi/lo) in m16n8k16 order
    const int w    = tid >> 5;
    const int lane = tid & 31;
    const int g = lane >> 2, t = lane & 3;
    const int er = w * 16 + g;

#pragma unroll
    for (int kt = 0; kt < 4; ++kt) {
        const int k0 = kt * 16 + 2 * t;
        const float* b0 = sHa + (k0)     * HT;
        const float* b1 = sHa + (k0 + 1) * HT;
        const float* b8 = sHa + (k0 + 8) * HT;
        const float* b9 = sHa + (k0 + 9) * HT;
        uint4 vh, vl;
        split_pack(b0[er],     b1[er],     vh.x, vl.x);
        split_pack(b0[er + 8], b1[er + 8], vh.y, vl.y);
        split_pack(b8[er],     b9[er],     vh.z, vl.z);
        split_pack(b8[er + 8], b9[er + 8], vh.w, vl.w);
        const int idx = ((blk * 8 + w) * 4 + kt) * 32 + lane;
        g_ah4[idx] = vh;
        g_al4[idx] = vl;
    }
}

// ---------------------------------------------------------------------------
// Kernel 2: zero the aggregation buffer (float4)
// ---------------------------------------------------------------------------
__global__ void __launch_bounds__(256)
zero_kernel()
{
    const size_t i = (size_t)blockIdx.x * 256 + threadIdx.x;
    ((float4*)g_agg)[i] = make_float4(0.f, 0.f, 0.f, 0.f);
}

// ---------------------------------------------------------------------------
// Kernel 3: FUSED GEMM4 + tensor-product messages + scatter (chunked).
// R7 structure + interleaved g_agg [node][c][4] scatter (best measured 259us).
// ---------------------------------------------------------------------------
__global__ void __launch_bounds__(256, 2)
fused_kernel(const float* __restrict__ nf, const float* __restrict__ ef,
             const float* __restrict__ attrs,
             const int* __restrict__ snd, const int* __restrict__ rcv,
             int blk0)
{
    __shared__ int    s_snd[8][16];
    __shared__ int    s_rcv[8][16];
    __shared__ float4 s_y[8][32 * 5];   // per warp: 32 consumer lanes x 5 slots (pad)

    const int tid  = threadIdx.x;
    const int w    = tid >> 5;
    const int lane = tid & 31;
    const int gr   = lane >> 2;
    const int t    = lane & 3;
    const int blk = blk0 + blockIdx.x;
    const size_t e0 = (size_t)blk * 128;

    if (lane < 16) {
        s_snd[w][lane] = snd[e0 + (size_t)(w * 16 + lane)];
        s_rcv[w][lane] = rcv[e0 + (size_t)(w * 16 + lane)];
    }
    __syncwarp();

    // this lane's message edge (fixed across tiles)
    const int eml = gr + 8 * (t & 1);
    const size_t em = e0 + (size_t)(w * 16 + eml);
    const float4 sh = *(const float4*)(attrs + em * 4);
    const float sh0 = sh.x, s1x = sh.y, s1y = sh.z, s1z = sh.w;
    float* pagg = g_agg + (size_t)s_rcv[w][eml] * DD;

    // producer-role constants: this lane stages float4 piece jP of 4 edges
    const int jP = lane & 7;
    const int ch4P  = (jP < 2) ? jP : (jP - 2) / 3;
    const int slotP = (jP < 2) ? 0 : ((jP - 2) % 3) + 1;
    const int offMul = (jP < 2) ? 8 : 24;
    const int offAdd = (jP < 2) ? jP * 4 : CC + (jP - 2) * 4;
    const int elBase = lane >> 3;       // + 4*it

    // load resident A fragments
    uint32_t Ah[4][4], Al[4][4];
#pragma unroll
    for (int kt = 0; kt < 4; ++kt) {
        const int idx = ((blk * 8 + w) * 4 + kt) * 32 + lane;
        const uint4 vh = g_ah4[idx];
        const uint4 vl = g_al4[idx];
        Ah[kt][0] = vh.x; Ah[kt][1] = vh.y; Ah[kt][2] = vh.z; Ah[kt][3] = vh.w;
        Al[kt][0] = vl.x; Al[kt][1] = vl.y; Al[kt][2] = vl.z; Al[kt][3] = vl.w;
    }

#pragma unroll 1
    for (int tile = 0; tile < 16; ++tile) {
        // 1) issue staging loads first (latency hidden under HMMA below)
        const int off = tile * offMul + offAdd;
        float4 xa[4], xb[4], xc[4];
#pragma unroll
        for (int it = 0; it < 4; ++it) {
            const int el = it * 4 + elBase;
            xa[it] = __ldg((const float4*)(nf + (size_t)s_snd[w][el] * DD + off));
            xb[it] = __ldg((const float4*)(nf + (size_t)s_rcv[w][el] * DD + off));
            xc[it] = __ldg((const float4*)(ef + (e0 + (size_t)(w * 16 + el)) * DD + off));
        }

        // 2) HMMA: 5 radial chunks, 3-term bf16 split
        float acc[5][4];
#pragma unroll
        for (int q = 0; q < 5; ++q)
#pragma unroll
            for (int i = 0; i < 4; ++i) acc[q][i] = 0.f;

#pragma unroll
        for (int q = 0; q < 5; ++q) {
#pragma unroll
            for (int kt = 0; kt < 4; ++kt) {
                const uint4 bb = __ldg(g_b4 + ((kt * 80 + q * 16 + tile) * 32 + lane));
                mma_bf16(acc[q], Ah[kt], bb.x, bb.y);
                mma_bf16(acc[q], Al[kt], bb.x, bb.y);
                mma_bf16(acc[q], Ah[kt], bb.z, bb.w);
            }
        }

        // 3) sum + store into consumer slots
#pragma unroll
        for (int it = 0; it < 4; ++it) {
            const int el = it * 4 + elBase;
            const int c = (el & 7) * 4 + (el >> 3) + 2 * ch4P;
            s_y[w][c * 5 + slotP] = make_float4(
                xa[it].x + xb[it].x + xc[it].x,
                xa[it].y + xb[it].y + xc[it].y,
                xa[it].z + xb[it].z + xc[it].z,
                xa[it].w + xb[it].w + xc[it].w);
        }
        __syncwarp();

        // 4) read own x pieces
        const float4* my = &s_y[w][lane * 5];
        const float4 X0 = my[0];
        const float4 V0 = my[1];
        const float4 V1 = my[2];
        const float4 V2 = my[3];
        const float x0[4]  = {X0.x, X0.y, X0.z, X0.w};
        const float xv[12] = {V0.x, V0.y, V0.z, V0.w,
                              V1.x, V1.y, V1.z, V1.w,
                              V2.x, V2.y, V2.z, V2.w};

        // 5) redistribute HMMA fragments: lane -> (edge em, channels cm..cm+3)
#pragma unroll
        for (int q = 0; q < 5; ++q) {
            const float s0 = (t & 1) ? acc[q][0] : acc[q][2];
            const float s1 = (t & 1) ? acc[q][1] : acc[q][3];
            const float r0 = __shfl_xor_sync(0xffffffffu, s0, 1);
            const float r1 = __shfl_xor_sync(0xffffffffu, s1, 1);
            if (t & 1) { acc[q][0] = r0; acc[q][1] = r1; }
            else       { acc[q][2] = r0; acc[q][3] = r1; }
        }
        const int cm = tile * 8 + (t >> 1) * 4;

        // 6) messages -> interleaved red: per channel j, one red.v4 of
        // (m0, m1x, m1y, m1z) at pagg + (cm+j)*4  (64B contiguous per lane)
#pragma unroll
        for (int j = 0; j < 4; ++j) {
            const float u0 = xv[3 * j], u1 = xv[3 * j + 1], u2 = xv[3 * j + 2];
            const float dot = u0 * s1x + u1 * s1y + u2 * s1z;
            const float m0 = acc[0][j] * x0[j] * sh0 + acc[1][j] * dot * INV_SQRT3;
            const float cx = u1 * s1z - u2 * s1y;
            const float cy = u2 * s1x - u0 * s1z;
            const float cz = u0 * s1y - u1 * s1x;
            const float mx = acc[2][j] * u0 * sh0 + acc[3][j] * x0[j] * s1x + acc[4][j] * cx * INV_SQRT2;
            const float my2 = acc[2][j] * u1 * sh0 + acc[3][j] * x0[j] * s1y + acc[4][j] * cy * INV_SQRT2;
            const float mz = acc[2][j] * u2 * sh0 + acc[3][j] * x0[j] * s1z + acc[4][j] * cz * INV_SQRT2;
            asm volatile("red.global.add.v4.f32 [%0], {%1,%2,%3,%4};"
                         :: "l"(pagg + (size_t)(cm + j) * 4),
                            "f"(m0), "f"(mx), "f"(my2), "f"(mz)
                         : "memory");
        }
        __syncwarp();
    }
}

// ---------------------------------------------------------------------------
// Kernel 4: out = agg + eq_linear(agg,res) + eq_linear(nf,skip).
// 128 threads, 16 nodes/block, 4 nodes/thread, bank-staggered plane arrays.
// ---------------------------------------------------------------------------
#define OST 18
#define AST (CC * OST + 8)      // 2312: plane-array stride, bank-staggered

__global__ void __launch_bounds__(128)
out_kernel(const float* __restrict__ nf,
           const float* __restrict__ rW0, const float* __restrict__ rW1,
           const float* __restrict__ skW0, const float* __restrict__ skW1,
           float* __restrict__ out)
{
    extern __shared__ float osm[];
    float* sA0 = osm;
    float* sN0 = osm + 4 * AST;

    const int tid = threadIdx.x;
    const size_t n0 = (size_t)blockIdx.x * 16;

    // agg fill: one float4 per (node, c) — coalesced 16B x 32 lanes
    {
        const float4* agg4 = (const float4*)(g_agg + n0 * DD);
        for (int i = tid; i < 16 * CC; i += 128) {
            const int n = i >> 7;
            const int c = i & 127;
            const float4 v = agg4[n * CC + c];
            sA0[c * OST + n]           = v.x;
            sA0[AST + c * OST + n]     = v.y;
            sA0[2 * AST + c * OST + n] = v.z;
            sA0[3 * AST + c * OST + n] = v.w;
        }
    }
    // nf fill (original layout)
    for (int i = tid; i < 16 * DD; i += 128) {
        const int n = i >> 9;
        const int q = i & 511;
        const float vb = nf[(n0 + n) * DD + q];
        if (q < CC) {
            sN0[q * OST + n] = vb;
        } else {
            const int rr = q - CC;
            const int c = rr / 3;
            const int ax = rr - 3 * c;
            sN0[(1 + ax) * AST + c * OST + n] = vb;
        }
    }
    __syncthreads();

    const int dg = tid & 31;
    const int ng = tid >> 5;          // 0..3
    const int d0 = dg * 4;
    const int nb = ng * 4;            // this thread's 4 nodes: nb..nb+3

    u64 acc0[2][4], accx[2][4], accy[2][4], accz[2][4];
#pragma unroll
    for (int p = 0; p < 2; ++p)
#pragma unroll
        for (int d = 0; d < 4; ++d) {
            acc0[p][d] = 0ull; accx[p][d] = 0ull;
            accy[p][d] = 0ull; accz[p][d] = 0ull;
        }

#pragma unroll 2
    for (int c = 0; c < CC; ++c) {
        const float4 wr0 = __ldg((const float4*)(rW0  + c * CC + d0));
        const float4 ws0 = __ldg((const float4*)(skW0 + c * CC + d0));
        const float4 wr1 = __ldg((const float4*)(rW1  + c * CC + d0));
        const float4 ws1 = __ldg((const float4*)(skW1 + c * CC + d0));
        const float r0a[4] = {wr0.x, wr0.y, wr0.z, wr0.w};
        const float s0a[4] = {ws0.x, ws0.y, ws0.z, ws0.w};
        const float r1a[4] = {wr1.x, wr1.y, wr1.z, wr1.w};
        const float s1a[4] = {ws1.x, ws1.y, ws1.z, ws1.w};
        u64 pr0[4], ps0[4], pr1[4], ps1[4];
#pragma unroll
        for (int d = 0; d < 4; ++d) {
            pr0[d] = pack2(r0a[d], r0a[d]);
            ps0[d] = pack2(s0a[d], s0a[d]);
            pr1[d] = pack2(r1a[d], r1a[d]);
            ps1[d] = pack2(s1a[d], s1a[d]);
        }
#pragma unroll
        for (int p = 0; p < 2; ++p) {
            const int ab = c * OST + nb + p * 2;
            const u64 pA0 = *(const u64*)(sA0 + ab);
            const u64 pAx = *(const u64*)(sA0 + AST + ab);
            const u64 pAy = *(const u64*)(sA0 + 2 * AST + ab);
            const u64 pAz = *(const u64*)(sA0 + 3 * AST + ab);
            const u64 pN0 = *(const u64*)(sN0 + ab);
            const u64 pNx = *(const u64*)(sN0 + AST + ab);
            const u64 pNy = *(const u64*)(sN0 + 2 * AST + ab);
            const u64 pNz = *(const u64*)(sN0 + 3 * AST + ab);
#pragma unroll
            for (int d = 0; d < 4; ++d) {
                fma2(acc0[p][d], pA0, pr0[d]); fma2(acc0[p][d], pN0, ps0[d]);
                fma2(accx[p][d], pAx, pr1[d]); fma2(accx[p][d], pNx, ps1[d]);
                fma2(accy[p][d], pAy, pr1[d]); fma2(accy[p][d], pNy, ps1[d]);
                fma2(accz[p][d], pAz, pr1[d]); fma2(accz[p][d], pNz, ps1[d]);
            }
        }
    }

#pragma unroll
    for (int p = 0; p < 2; ++p) {
#pragma unroll
        for (int s = 0; s < 2; ++s) {
            const int n = nb + p * 2 + s;
            const size_t ob = (n0 + n) * DD;
            float o4[4], vv[12];
#pragma unroll
            for (int d = 0; d < 4; ++d) {
                float lo, hi, v;
                unpack2(acc0[p][d], lo, hi); v = s ? hi : lo;
                o4[d] = sA0[(d0 + d) * OST + n] + v * LIN_SCALE;
                unpack2(accx[p][d], lo, hi); v = s ? hi : lo;
                vv[3 * d + 0] = sA0[AST + (d0 + d) * OST + n] + v * LIN_SCALE;
                unpack2(accy[p][d], lo, hi); v = s ? hi : lo;
                vv[3 * d + 1] = sA0[2 * AST + (d0 + d) * OST + n] + v * LIN_SCALE;
                unpack2(accz[p][d], lo, hi); v = s ? hi : lo;
                vv[3 * d + 2] = sA0[3 * AST + (d0 + d) * OST + n] + v * LIN_SCALE;
            }
            *(float4*)(out + ob + d0) = make_float4(o4[0], o4[1], o4[2], o4[3]);
            float* vb = out + ob + CC + 3 * d0;
            *(float4*)(vb    ) = make_float4(vv[0], vv[1], vv[2],  vv[3]);
            *(float4*)(vb + 4) = make_float4(vv[4], vv[5], vv[6],  vv[7]);
            *(float4*)(vb + 8) = make_float4(vv[8], vv[9], vv[10], vv[11]);
        }
    }
}

// ---------------------------------------------------------------------------
extern "C" void kernel_launch(void* const* d_in, const int* in_sizes, int n_in,
                              void* d_out, int out_size)
{
    const float* nf    = (const float*)d_in[0];
    const float* ef    = (const float*)d_in[1];
    const float* attrs = (const float*)d_in[2];
    const float* emb   = (const float*)d_in[3];
    const int*   snd   = (const int*)d_in[4];
    const int*   rcv   = (const int*)d_in[5];
    const float* Wm1   = (const float*)d_in[6];
    const float* Wm2   = (const float*)d_in[7];
    const float* Wm3   = (const float*)d_in[8];
    const float* Wm4   = (const float*)d_in[9];
    const float* rW0   = (const float*)d_in[10];
    const float* rW1   = (const float*)d_in[11];
    const float* sW0   = (const float*)d_in[12];
    const float* sW1   = (const float*)d_in[13];
    float* out = (float*)d_out;

    const int mlp_smem = (1536 + 2 * HH * HT) * 4;   // 72704 B
    const int out_smem = 8 * AST * 4;                // 73984 B

    static cudaStream_t s2;
    static cudaEvent_t evFork, evJoin, evM[NCH];
    static bool init_done = false;
    if (!init_done) {
        cudaFuncSetAttribute(mlp_kernel, cudaFuncAttributeMaxDynamicSharedMemorySize, mlp_smem);
        cudaFuncSetAttribute(out_kernel, cudaFuncAttributeMaxDynamicSharedMemorySize, out_smem);
        cudaStreamCreateWithFlags(&s2, cudaStreamNonBlocking);
        cudaEventCreateWithFlags(&evFork, cudaEventDisableTiming);
        cudaEventCreateWithFlags(&evJoin, cudaEventDisableTiming);
        for (int q = 0; q < NCH; ++q)
            cudaEventCreateWithFlags(&evM[q], cudaEventDisableTiming);
        init_done = true;
    }

    // fork side stream; zero+prep run there (hidden under mlp chunk 0)
    cudaEventRecord(evFork, 0);
    cudaStreamWaitEvent(s2, evFork, 0);
    zero_kernel<<<(NN * DD) / (256 * 4), 256, 0, s2>>>();
    prep_b4_kernel<<<(4 * 80 * 32 + 255) / 256, 256, 0, s2>>>(Wm4);

    // default stream: mlp chunks; s2: fused chunk q after mlp chunk q
    for (int q = 0; q < NCH; ++q) {
        mlp_kernel<<<CBLK, 256, mlp_smem>>>(emb, Wm1, Wm2, Wm3, q * CBLK);
        cudaEventRecord(evM[q], 0);
        cudaStreamWaitEvent(s2, evM[q], 0);
        fused_kernel<<<CBLK, 256, 0, s2>>>(nf, ef, attrs, snd, rcv, q * CBLK);
    }

    // join: out needs all fused chunks
    cudaEventRecord(evJoin, s2);
    cudaStreamWaitEvent(0, evJoin, 0);
    out_kernel<<<NN / 16, 128, out_smem>>>(nf, rW0, rW1, sW0, sW1, out);
}

// round 15
// speedup vs baseline: 1.2158x; 1.2158x over previous
#include <cuda_runtime.h>
#include <cuda_bf16.h>
#include <cstdint>

#define NN 10000
#define EE 160000
#define CC 128
#define DD 512
#define HH 64
#define W4C 640
#define HT 130   // padded stride for transposed h tiles [k][e]

#define INV_SQRT3 0.57735026918962576f
#define INV_SQRT2 0.70710678118654752f
#define LIN_SCALE 0.088388347648318447f   // 1/sqrt(128)

// Scratch (device globals; no runtime alloc)
// g_agg layout: [node][channel c (128)][4] where 4 = (m0, m1x, m1y, m1z)
__device__ float g_agg[(size_t)NN * DD];
__device__ uint4 g_ah4[1250 * 8 * 4 * 32];
__device__ uint4 g_al4[1250 * 8 * 4 * 32];
__device__ uint4 g_b4[4 * 80 * 32];
// out-transform weights, bf16 split, B-fragment order:
// [set(2)][kt(16)][nt(16)][lane(32)] uint4{h0,h1,l0,l1}
// set 0 = [rW0; skW0], set 1 = [rW1; skW1]  (K = 256: agg block then nf block)
__device__ uint4 g_ob4[2 * 16 * 16 * 32];

typedef unsigned long long u64;

__device__ __forceinline__ u64 pack2(float lo, float hi) {
    u64 r; asm("mov.b64 %0, {%1, %2};" : "=l"(r) : "f"(lo), "f"(hi)); return r;
}
__device__ __forceinline__ void unpack2(u64 v, float& lo, float& hi) {
    asm("mov.b64 {%0, %1}, %2;" : "=f"(lo), "=f"(hi) : "l"(v));
}
__device__ __forceinline__ void fma2(u64& d, u64 a, u64 b) {
    asm("fma.rn.f32x2 %0, %1, %2, %0;" : "+l"(d) : "l"(a), "l"(b));
}
__device__ __forceinline__ float silu_f(float x) { return x / (1.0f + __expf(-x)); }

__device__ __forceinline__ uint32_t pack_bf16(__nv_bfloat16 first, __nv_bfloat16 second) {
    return (uint32_t)__bfloat16_as_ushort(first) | ((uint32_t)__bfloat16_as_ushort(second) << 16);
}
__device__ __forceinline__ void split_pack(float x, float y, uint32_t& hi, uint32_t& lo) {
    const __nv_bfloat16 bx = __float2bfloat16(x);
    const __nv_bfloat16 by = __float2bfloat16(y);
    const __nv_bfloat16 rx = __float2bfloat16(x - __bfloat162float(bx));
    const __nv_bfloat16 ry = __float2bfloat16(y - __bfloat162float(by));
    hi = pack_bf16(bx, by);
    lo = pack_bf16(rx, ry);
}

__device__ __forceinline__ void mma_bf16(float* c, const uint32_t* a, uint32_t b0, uint32_t b1) {
    asm volatile("mma.sync.aligned.m16n8k16.row.col.f32.bf16.bf16.f32 "
        "{%0,%1,%2,%3}, {%4,%5,%6,%7}, {%8,%9}, {%0,%1,%2,%3};"
        : "+f"(c[0]), "+f"(c[1]), "+f"(c[2]), "+f"(c[3])
        : "r"(a[0]), "r"(a[1]), "r"(a[2]), "r"(a[3]), "r"(b0), "r"(b1));
}

// ---------------------------------------------------------------------------
// prep: split Wm4 -> bf16 hi/lo in B-fragment order.
// ---------------------------------------------------------------------------
__global__ void __launch_bounds__(256)
prep_b4_kernel(const float* __restrict__ Wm4)
{
    const int tid = blockIdx.x * 256 + threadIdx.x;
    if (tid >= 4 * 80 * 32) return;
    const int lane = tid & 31;
    const int idx = tid >> 5;
    const int kt = idx / 80, nt = idx % 80;
    const int g = lane >> 2, t = lane & 3;
    const int n = nt * 8 + g;
    const int k0 = kt * 16 + 2 * t;

    const float v00 = Wm4[(k0)     * W4C + n];
    const float v01 = Wm4[(k0 + 1) * W4C + n];
    const float v10 = Wm4[(k0 + 8) * W4C + n];
    const float v11 = Wm4[(k0 + 9) * W4C + n];
    uint4 o;
    split_pack(v00, v01, o.x, o.z);
    split_pack(v10, v11, o.y, o.w);
    g_b4[idx * 32 + lane] = o;
}

// ---------------------------------------------------------------------------
// prep: out-transform weights [res; skip] -> bf16 split B-fragments, K=256.
// ---------------------------------------------------------------------------
__global__ void __launch_bounds__(256)
prep_ow_kernel(const float* __restrict__ rW0, const float* __restrict__ rW1,
               const float* __restrict__ skW0, const float* __restrict__ skW1)
{
    const int tid = blockIdx.x * 256 + threadIdx.x;
    if (tid >= 2 * 16 * 16 * 32) return;
    const int lane = tid & 31;
    const int idx = tid >> 5;           // s*256 + kt*16 + nt
    const int s = idx >> 8;
    const int kt = (idx >> 4) & 15;
    const int nt = idx & 15;
    const int g = lane >> 2, t = lane & 3;
    const int n = nt * 8 + g;

    const float* Wa = s ? rW1 : rW0;    // K rows 0..127   (agg part)
    const float* Wb = s ? skW1 : skW0;  // K rows 128..255 (nf part)

    float v[4];
#pragma unroll
    for (int q = 0; q < 4; ++q) {
        const int k = kt * 16 + 2 * t + (q & 1) + (q >> 1) * 8;
        v[q] = (k < 128) ? Wa[k * CC + n] : Wb[(k - 128) * CC + n];
    }
    uint4 o;
    split_pack(v[0], v[1], o.x, o.z);
    split_pack(v[2], v[3], o.y, o.w);
    g_ob4[idx * 32 + lane] = o;
}

// ---------------------------------------------------------------------------
// One 64->64 layer, register-blocked.
// ---------------------------------------------------------------------------
__device__ __forceinline__ void layer_rb(const float* __restrict__ W,
                                         const float* sIn, float* sOut,
                                         int jbase, int ebase)
{
    u64 acc[4][4];
#pragma unroll
    for (int c = 0; c < 4; ++c)
#pragma unroll
        for (int p = 0; p < 4; ++p) acc[c][p] = 0ull;

#pragma unroll 4
    for (int k = 0; k < HH; ++k) {
        const float4 w4 = __ldg((const float4*)(W + k * HH + jbase));
        const u64* hp = (const u64*)(sIn + k * HT + ebase);
        const u64 h0 = hp[0], h1 = hp[1], h2 = hp[2], h3 = hp[3];
        const float wv[4] = {w4.x, w4.y, w4.z, w4.w};
#pragma unroll
        for (int c = 0; c < 4; ++c) {
            const u64 w2 = pack2(wv[c], wv[c]);
            fma2(acc[c][0], h0, w2);
            fma2(acc[c][1], h1, w2);
            fma2(acc[c][2], h2, w2);
            fma2(acc[c][3], h3, w2);
        }
    }
#pragma unroll
    for (int c = 0; c < 4; ++c) {
        u64* op = (u64*)(sOut + (jbase + c) * HT + ebase);
#pragma unroll
        for (int p = 0; p < 4; ++p) {
            float lo, hi; unpack2(acc[c][p], lo, hi);
            op[p] = pack2(silu_f(lo), silu_f(hi));
        }
    }
}

// ---------------------------------------------------------------------------
// Kernel 1: MLP layers 1-3 (scalar) -> split bf16 A-fragments.
// ---------------------------------------------------------------------------
__global__ void __launch_bounds__(256, 2)
mlp_kernel(const float* __restrict__ emb, const float* __restrict__ Wm1,
           const float* __restrict__ Wm2, const float* __restrict__ Wm3)
{
    extern __shared__ float sm[];
    float* sE  = sm;
    float* sW1 = sm + 1024;
    float* sHa = sm + 1536;
    float* sHb = sm + 1536 + HH * HT;

    const int tid = threadIdx.x;
    const size_t e0 = (size_t)blockIdx.x * 128;

    for (int i = tid; i < 1024; i += 256) sE[i] = emb[e0 * 8 + i];
    for (int i = tid; i < 512; i += 256)  sW1[i] = Wm1[i];
    __syncthreads();

    const int jq = tid & 15;
    const int eg = tid >> 4;
    const int jbase = jq * 4;
    const int ebase = eg * 8;

    {
        float w[8][4];
#pragma unroll
        for (int r = 0; r < 8; ++r) {
            const float4 w4 = *(const float4*)(sW1 + r * HH + jbase);
            w[r][0] = w4.x; w[r][1] = w4.y; w[r][2] = w4.z; w[r][3] = w4.w;
        }
#pragma unroll
        for (int e = 0; e < 8; ++e) {
            const float4 ea = *(const float4*)(sE + (ebase + e) * 8);
            const float4 eb = *(const float4*)(sE + (ebase + e) * 8 + 4);
            const float er[8] = {ea.x, ea.y, ea.z, ea.w, eb.x, eb.y, eb.z, eb.w};
#pragma unroll
            for (int c = 0; c < 4; ++c) {
                float acc = 0.f;
#pragma unroll
                for (int r = 0; r < 8; ++r) acc += er[r] * w[r][c];
                sHa[(jbase + c) * HT + ebase + e] = silu_f(acc);
            }
        }
    }
    __syncthreads();
    layer_rb(Wm2, sHa, sHb, jbase, ebase);
    __syncthreads();
    layer_rb(Wm3, sHb, sHa, jbase, ebase);
    __syncthreads();

    const int w    = tid >> 5;
    const int lane = tid & 31;
    const int g = lane >> 2, t = lane & 3;
    const int er = w * 16 + g;

#pragma unroll
    for (int kt = 0; kt < 4; ++kt) {
        const int k0 = kt * 16 + 2 * t;
        const float* b0 = sHa + (k0)     * HT;
        const float* b1 = sHa + (k0 + 1) * HT;
        const float* b8 = sHa + (k0 + 8) * HT;
        const float* b9 = sHa + (k0 + 9) * HT;
        uint4 vh, vl;
        split_pack(b0[er],     b1[er],     vh.x, vl.x);
        split_pack(b0[er + 8], b1[er + 8], vh.y, vl.y);
        split_pack(b8[er],     b9[er],     vh.z, vl.z);
        split_pack(b8[er + 8], b9[er + 8], vh.w, vl.w);
        const int idx = ((blockIdx.x * 8 + w) * 4 + kt) * 32 + lane;
        g_ah4[idx] = vh;
        g_al4[idx] = vl;
    }
}

// ---------------------------------------------------------------------------
// Kernel 2: zero agg
// ---------------------------------------------------------------------------
__global__ void __launch_bounds__(256)
zero_kernel()
{
    const size_t i = (size_t)blockIdx.x * 256 + threadIdx.x;
    ((float4*)g_agg)[i] = make_float4(0.f, 0.f, 0.f, 0.f);
}

// ---------------------------------------------------------------------------
// Kernel 3: FUSED GEMM4 + messages + interleaved scatter (best: 259us).
// ---------------------------------------------------------------------------
__global__ void __launch_bounds__(256, 2)
fused_kernel(const float* __restrict__ nf, const float* __restrict__ ef,
             const float* __restrict__ attrs,
             const int* __restrict__ snd, const int* __restrict__ rcv)
{
    __shared__ int    s_snd[8][16];
    __shared__ int    s_rcv[8][16];
    __shared__ float4 s_y[8][32 * 5];

    const int tid  = threadIdx.x;
    const int w    = tid >> 5;
    const int lane = tid & 31;
    const int gr   = lane >> 2;
    const int t    = lane & 3;
    const size_t e0 = (size_t)blockIdx.x * 128;

    if (lane < 16) {
        s_snd[w][lane] = snd[e0 + (size_t)(w * 16 + lane)];
        s_rcv[w][lane] = rcv[e0 + (size_t)(w * 16 + lane)];
    }
    __syncwarp();

    const int eml = gr + 8 * (t & 1);
    const size_t em = e0 + (size_t)(w * 16 + eml);
    const float4 sh = *(const float4*)(attrs + em * 4);
    const float sh0 = sh.x, s1x = sh.y, s1y = sh.z, s1z = sh.w;
    float* pagg = g_agg + (size_t)s_rcv[w][eml] * DD;

    const int jP = lane & 7;
    const int ch4P  = (jP < 2) ? jP : (jP - 2) / 3;
    const int slotP = (jP < 2) ? 0 : ((jP - 2) % 3) + 1;
    const int offMul = (jP < 2) ? 8 : 24;
    const int offAdd = (jP < 2) ? jP * 4 : CC + (jP - 2) * 4;
    const int elBase = lane >> 3;

    uint32_t Ah[4][4], Al[4][4];
#pragma unroll
    for (int kt = 0; kt < 4; ++kt) {
        const int idx = ((blockIdx.x * 8 + w) * 4 + kt) * 32 + lane;
        const uint4 vh = g_ah4[idx];
        const uint4 vl = g_al4[idx];
        Ah[kt][0] = vh.x; Ah[kt][1] = vh.y; Ah[kt][2] = vh.z; Ah[kt][3] = vh.w;
        Al[kt][0] = vl.x; Al[kt][1] = vl.y; Al[kt][2] = vl.z; Al[kt][3] = vl.w;
    }

#pragma unroll 1
    for (int tile = 0; tile < 16; ++tile) {
        const int off = tile * offMul + offAdd;
        float4 xa[4], xb[4], xc[4];
#pragma unroll
        for (int it = 0; it < 4; ++it) {
            const int el = it * 4 + elBase;
            xa[it] = __ldg((const float4*)(nf + (size_t)s_snd[w][el] * DD + off));
            xb[it] = __ldg((const float4*)(nf + (size_t)s_rcv[w][el] * DD + off));
            xc[it] = __ldg((const float4*)(ef + (e0 + (size_t)(w * 16 + el)) * DD + off));
        }

        float acc[5][4];
#pragma unroll
        for (int q = 0; q < 5; ++q)
#pragma unroll
            for (int i = 0; i < 4; ++i) acc[q][i] = 0.f;

#pragma unroll
        for (int q = 0; q < 5; ++q) {
#pragma unroll
            for (int kt = 0; kt < 4; ++kt) {
                const uint4 bb = __ldg(g_b4 + ((kt * 80 + q * 16 + tile) * 32 + lane));
                mma_bf16(acc[q], Ah[kt], bb.x, bb.y);
                mma_bf16(acc[q], Al[kt], bb.x, bb.y);
                mma_bf16(acc[q], Ah[kt], bb.z, bb.w);
            }
        }

#pragma unroll
        for (int it = 0; it < 4; ++it) {
            const int el = it * 4 + elBase;
            const int c = (el & 7) * 4 + (el >> 3) + 2 * ch4P;
            s_y[w][c * 5 + slotP] = make_float4(
                xa[it].x + xb[it].x + xc[it].x,
                xa[it].y + xb[it].y + xc[it].y,
                xa[it].z + xb[it].z + xc[it].z,
                xa[it].w + xb[it].w + xc[it].w);
        }
        __syncwarp();

        const float4* my = &s_y[w][lane * 5];
        const float4 X0 = my[0];
        const float4 V0 = my[1];
        const float4 V1 = my[2];
        const float4 V2 = my[3];
        const float x0[4]  = {X0.x, X0.y, X0.z, X0.w};
        const float xv[12] = {V0.x, V0.y, V0.z, V0.w,
                              V1.x, V1.y, V1.z, V1.w,
                              V2.x, V2.y, V2.z, V2.w};

#pragma unroll
        for (int q = 0; q < 5; ++q) {
            const float s0 = (t & 1) ? acc[q][0] : acc[q][2];
            const float s1 = (t & 1) ? acc[q][1] : acc[q][3];
            const float r0 = __shfl_xor_sync(0xffffffffu, s0, 1);
            const float r1 = __shfl_xor_sync(0xffffffffu, s1, 1);
            if (t & 1) { acc[q][0] = r0; acc[q][1] = r1; }
            else       { acc[q][2] = r0; acc[q][3] = r1; }
        }
        const int cm = tile * 8 + (t >> 1) * 4;

#pragma unroll
        for (int j = 0; j < 4; ++j) {
            const float u0 = xv[3 * j], u1 = xv[3 * j + 1], u2 = xv[3 * j + 2];
            const float dot = u0 * s1x + u1 * s1y + u2 * s1z;
            const float m0 = acc[0][j] * x0[j] * sh0 + acc[1][j] * dot * INV_SQRT3;
            const float cx = u1 * s1z - u2 * s1y;
            const float cy = u2 * s1x - u0 * s1z;
            const float cz = u0 * s1y - u1 * s1x;
            const float mx = acc[2][j] * u0 * sh0 + acc[3][j] * x0[j] * s1x + acc[4][j] * cx * INV_SQRT2;
            const float my2 = acc[2][j] * u1 * sh0 + acc[3][j] * x0[j] * s1y + acc[4][j] * cy * INV_SQRT2;
            const float mz = acc[2][j] * u2 * sh0 + acc[3][j] * x0[j] * s1z + acc[4][j] * cz * INV_SQRT2;
            asm volatile("red.global.add.v4.f32 [%0], {%1,%2,%3,%4};"
                         :: "l"(pagg + (size_t)(cm + j) * 4),
                            "f"(m0), "f"(mx), "f"(my2), "f"(mz)
                         : "memory");
        }
        __syncwarp();
    }
}

// ---------------------------------------------------------------------------
// Kernel 4: out via tensor cores. Grid (157, 4): 64 nodes x plane per block.
// X = [agg_plane | nf_plane] (K=256) staged in smem; 3-term bf16 HMMA;
// epilogue adds agg residual from smem and stores.
// ---------------------------------------------------------------------------
#define XST 260                       // smem row stride (floats), 260%32=4
#define OUT_SMEM (64 * XST * 4)       // 66560 B

__global__ void __launch_bounds__(256)
out_tc_kernel(const float* __restrict__ nf, float* __restrict__ out)
{
    extern __shared__ float Xs[];     // [64][XST]: cols 0..127 agg, 128..255 nf

    const int tid = threadIdx.x;
    const int p = blockIdx.y;                 // plane 0..3
    const size_t n0 = (size_t)blockIdx.x * 64;

    // stage agg plane (cols 0..127)
    for (int i = tid; i < 64 * CC; i += 256) {
        const int n = i >> 7;
        const int c = i & 127;
        float v = 0.f;
        if (n0 + n < NN) v = g_agg[(n0 + n) * DD + c * 4 + p];
        Xs[n * XST + c] = v;
    }
    // stage nf plane (cols 128..255)
    for (int i = tid; i < 64 * CC; i += 256) {
        const int n = i >> 7;
        const int c = i & 127;
        float v = 0.f;
        if (n0 + n < NN) {
            const int col = (p == 0) ? c : (CC + 3 * c + (p - 1));
            v = nf[(n0 + n) * DD + col];
        }
        Xs[n * XST + 128 + c] = v;
    }
    __syncthreads();

    const int w    = tid >> 5;
    const int lane = tid & 31;
    const int mg   = w & 3;           // m16 row group
    const int nh   = w >> 2;          // n half (64 cols)
    const int g = lane >> 2, t = lane & 3;
    const int rA = mg * 16 + g;       // fragment rows rA, rA+8
    const int s = (p == 0) ? 0 : 1;   // weight set

    float acc[8][4];
#pragma unroll
    for (int nt8 = 0; nt8 < 8; ++nt8)
#pragma unroll
        for (int i = 0; i < 4; ++i) acc[nt8][i] = 0.f;

#pragma unroll 1
    for (int kt = 0; kt < 16; ++kt) {
        // build A fragment from smem
        const int k = kt * 16 + 2 * t;
        const float* r0 = Xs + rA * XST;
        const float* r8 = Xs + (rA + 8) * XST;
        uint32_t Ah[4], Al[4];
        split_pack(r0[k],     r0[k + 1], Ah[0], Al[0]);
        split_pack(r8[k],     r8[k + 1], Ah[1], Al[1]);
        split_pack(r0[k + 8], r0[k + 9], Ah[2], Al[2]);
        split_pack(r8[k + 8], r8[k + 9], Ah[3], Al[3]);

#pragma unroll
        for (int nt8 = 0; nt8 < 8; ++nt8) {
            const int nt = nh * 8 + nt8;
            const uint4 bb = __ldg(g_ob4 + ((s * 16 + kt) * 16 + nt) * 32 + lane);
            mma_bf16(acc[nt8], Ah, bb.x, bb.y);
            mma_bf16(acc[nt8], Al, bb.x, bb.y);
            mma_bf16(acc[nt8], Ah, bb.z, bb.w);
        }
    }

    // epilogue: out = agg_residual + LIN_SCALE * acc
#pragma unroll
    for (int nt8 = 0; nt8 < 8; ++nt8) {
        const int d0 = nh * 64 + nt8 * 8 + 2 * t;
#pragma unroll
        for (int half = 0; half < 2; ++half) {
            const int r = rA + half * 8;
            if (n0 + r >= NN) continue;
            const float v0 = Xs[r * XST + d0]     + acc[nt8][half * 2]     * LIN_SCALE;
            const float v1 = Xs[r * XST + d0 + 1] + acc[nt8][half * 2 + 1] * LIN_SCALE;
            float* ob = out + (n0 + r) * DD;
            if (p == 0) {
                *(float2*)(ob + d0) = make_float2(v0, v1);
            } else {
                ob[CC + 3 * d0 + (p - 1)]       = v0;
                ob[CC + 3 * (d0 + 1) + (p - 1)] = v1;
            }
        }
    }
}

// ---------------------------------------------------------------------------
extern "C" void kernel_launch(void* const* d_in, const int* in_sizes, int n_in,
                              void* d_out, int out_size)
{
    const float* nf    = (const float*)d_in[0];
    const float* ef    = (const float*)d_in[1];
    const float* attrs = (const float*)d_in[2];
    const float* emb   = (const float*)d_in[3];
    const int*   snd   = (const int*)d_in[4];
    const int*   rcv   = (const int*)d_in[5];
    const float* Wm1   = (const float*)d_in[6];
    const float* Wm2   = (const float*)d_in[7];
    const float* Wm3   = (const float*)d_in[8];
    const float* Wm4   = (const float*)d_in[9];
    const float* rW0   = (const float*)d_in[10];
    const float* rW1   = (const float*)d_in[11];
    const float* sW0   = (const float*)d_in[12];
    const float* sW1   = (const float*)d_in[13];
    float* out = (float*)d_out;

    const int mlp_smem = (1536 + 2 * HH * HT) * 4;   // 72704 B
    static bool attr_done = false;
    if (!attr_done) {
        cudaFuncSetAttribute(mlp_kernel, cudaFuncAttributeMaxDynamicSharedMemorySize, mlp_smem);
        cudaFuncSetAttribute(out_tc_kernel, cudaFuncAttributeMaxDynamicSharedMemorySize, OUT_SMEM);
        attr_done = true;
    }

    zero_kernel<<<(NN * DD) / (256 * 4), 256>>>();
    prep_b4_kernel<<<(4 * 80 * 32 + 255) / 256, 256>>>(Wm4);
    prep_ow_kernel<<<(2 * 16 * 16 * 32 + 255) / 256, 256>>>(rW0, rW1, sW0, sW1);
    mlp_kernel<<<EE / 128, 256, mlp_smem>>>(emb, Wm1, Wm2, Wm3);
    fused_kernel<<<EE / 128, 256>>>(nf, ef, attrs, snd, rcv);
    out_tc_kernel<<<dim3((NN + 63) / 64, 4), 256, OUT_SMEM>>>(nf, out);
}

// round 16
// speedup vs baseline: 1.3037x; 1.0724x over previous
#include <cuda_runtime.h>
#include <cuda_bf16.h>
#include <cstdint>

#define NN 10000
#define EE 160000
#define CC 128
#define DD 512
#define HH 64
#define W4C 640
#define HT 130   // padded stride for transposed h tiles [k][e]

#define INV_SQRT3 0.57735026918962576f
#define INV_SQRT2 0.70710678118654752f
#define LIN_SCALE 0.088388347648318447f   // 1/sqrt(128)

// Scratch (device globals; no runtime alloc)
// g_agg layout: [node][channel c (128)][4] where 4 = (m0, m1x, m1y, m1z)
__device__ float g_agg[(size_t)NN * DD];
__device__ uint4 g_ah4[1250 * 8 * 4 * 32];
__device__ uint4 g_al4[1250 * 8 * 4 * 32];
__device__ uint4 g_b4[4 * 80 * 32];
// out-transform weights, bf16 split, B-fragment order (K=256)
__device__ uint4 g_ob4[2 * 16 * 16 * 32];
// Wm2/Wm3 split bf16 B-fragments: [layer(2)][kt(4)][nt(8)][lane(32)]
__device__ uint4 g_b23[2 * 4 * 8 * 32];

typedef unsigned long long u64;

__device__ __forceinline__ u64 pack2(float lo, float hi) {
    u64 r; asm("mov.b64 %0, {%1, %2};" : "=l"(r) : "f"(lo), "f"(hi)); return r;
}
__device__ __forceinline__ void unpack2(u64 v, float& lo, float& hi) {
    asm("mov.b64 {%0, %1}, %2;" : "=f"(lo), "=f"(hi) : "l"(v));
}
__device__ __forceinline__ void fma2(u64& d, u64 a, u64 b) {
    asm("fma.rn.f32x2 %0, %1, %2, %0;" : "+l"(d) : "l"(a), "l"(b));
}
__device__ __forceinline__ float silu_f(float x) { return x / (1.0f + __expf(-x)); }

__device__ __forceinline__ uint32_t pack_bf16(__nv_bfloat16 first, __nv_bfloat16 second) {
    return (uint32_t)__bfloat16_as_ushort(first) | ((uint32_t)__bfloat16_as_ushort(second) << 16);
}
__device__ __forceinline__ void split_pack(float x, float y, uint32_t& hi, uint32_t& lo) {
    const __nv_bfloat16 bx = __float2bfloat16(x);
    const __nv_bfloat16 by = __float2bfloat16(y);
    const __nv_bfloat16 rx = __float2bfloat16(x - __bfloat162float(bx));
    const __nv_bfloat16 ry = __float2bfloat16(y - __bfloat162float(by));
    hi = pack_bf16(bx, by);
    lo = pack_bf16(rx, ry);
}

__device__ __forceinline__ void mma_bf16(float* c, const uint32_t* a, uint32_t b0, uint32_t b1) {
    asm volatile("mma.sync.aligned.m16n8k16.row.col.f32.bf16.bf16.f32 "
        "{%0,%1,%2,%3}, {%4,%5,%6,%7}, {%8,%9}, {%0,%1,%2,%3};"
        : "+f"(c[0]), "+f"(c[1]), "+f"(c[2]), "+f"(c[3])
        : "r"(a[0]), "r"(a[1]), "r"(a[2]), "r"(a[3]), "r"(b0), "r"(b1));
}

// ---------------------------------------------------------------------------
// prep: split Wm4 -> bf16 hi/lo in B-fragment order.
// ---------------------------------------------------------------------------
__global__ void __launch_bounds__(256)
prep_b4_kernel(const float* __restrict__ Wm4)
{
    const int tid = blockIdx.x * 256 + threadIdx.x;
    if (tid >= 4 * 80 * 32) return;
    const int lane = tid & 31;
    const int idx = tid >> 5;
    const int kt = idx / 80, nt = idx % 80;
    const int g = lane >> 2, t = lane & 3;
    const int n = nt * 8 + g;
    const int k0 = kt * 16 + 2 * t;

    const float v00 = Wm4[(k0)     * W4C + n];
    const float v01 = Wm4[(k0 + 1) * W4C + n];
    const float v10 = Wm4[(k0 + 8) * W4C + n];
    const float v11 = Wm4[(k0 + 9) * W4C + n];
    uint4 o;
    split_pack(v00, v01, o.x, o.z);
    split_pack(v10, v11, o.y, o.w);
    g_b4[idx * 32 + lane] = o;
}

// ---------------------------------------------------------------------------
// prep: Wm2/Wm3 -> bf16 split B-fragments (64x64 each).
// ---------------------------------------------------------------------------
__global__ void __launch_bounds__(256)
prep_b23_kernel(const float* __restrict__ Wm2, const float* __restrict__ Wm3)
{
    const int tid = blockIdx.x * 256 + threadIdx.x;
    if (tid >= 2 * 4 * 8 * 32) return;
    const int lane = tid & 31;
    const int idx = tid >> 5;           // layer*32 + kt*8 + nt
    const int layer = idx >> 5;
    const int kt = (idx >> 3) & 3;
    const int nt = idx & 7;
    const int g = lane >> 2, t = lane & 3;
    const int n = nt * 8 + g;
    const int k0 = kt * 16 + 2 * t;
    const float* W = layer ? Wm3 : Wm2;

    const float v00 = W[(k0)     * HH + n];
    const float v01 = W[(k0 + 1) * HH + n];
    const float v10 = W[(k0 + 8) * HH + n];
    const float v11 = W[(k0 + 9) * HH + n];
    uint4 o;
    split_pack(v00, v01, o.x, o.z);
    split_pack(v10, v11, o.y, o.w);
    g_b23[idx * 32 + lane] = o;
}

// ---------------------------------------------------------------------------
// prep: out-transform weights [res; skip] -> bf16 split B-fragments, K=256.
// ---------------------------------------------------------------------------
__global__ void __launch_bounds__(256)
prep_ow_kernel(const float* __restrict__ rW0, const float* __restrict__ rW1,
               const float* __restrict__ skW0, const float* __restrict__ skW1)
{
    const int tid = blockIdx.x * 256 + threadIdx.x;
    if (tid >= 2 * 16 * 16 * 32) return;
    const int lane = tid & 31;
    const int idx = tid >> 5;           // s*256 + kt*16 + nt
    const int s = idx >> 8;
    const int kt = (idx >> 4) & 15;
    const int nt = idx & 15;
    const int g = lane >> 2, t = lane & 3;
    const int n = nt * 8 + g;

    const float* Wa = s ? rW1 : rW0;
    const float* Wb = s ? skW1 : skW0;

    float v[4];
#pragma unroll
    for (int q = 0; q < 4; ++q) {
        const int k = kt * 16 + 2 * t + (q & 1) + (q >> 1) * 8;
        v[q] = (k < 128) ? Wa[k * CC + n] : Wb[(k - 128) * CC + n];
    }
    uint4 o;
    split_pack(v[0], v[1], o.x, o.z);
    split_pack(v[2], v[3], o.y, o.w);
    g_ob4[idx * 32 + lane] = o;
}

// ---------------------------------------------------------------------------
// HMMA 64->64 layer (3-term bf16 split) + silu; transposed smem in/out.
// Per warp: rows er, er+8 over 8 n-tiles.
// ---------------------------------------------------------------------------
__device__ __forceinline__ void layer_hmma(const uint4* __restrict__ gB,
                                           const float* sIn, float* sOut,
                                           int w, int lane)
{
    const int g = lane >> 2, t = lane & 3;
    const int er = w * 16 + g;

    float acc[8][4];
#pragma unroll
    for (int nt = 0; nt < 8; ++nt)
#pragma unroll
        for (int i = 0; i < 4; ++i) acc[nt][i] = 0.f;

#pragma unroll
    for (int kt = 0; kt < 4; ++kt) {
        const int k0 = kt * 16 + 2 * t;
        const float* b0 = sIn + (k0)     * HT;
        const float* b1 = sIn + (k0 + 1) * HT;
        const float* b8 = sIn + (k0 + 8) * HT;
        const float* b9 = sIn + (k0 + 9) * HT;
        uint32_t Ah[4], Al[4];
        split_pack(b0[er],     b1[er],     Ah[0], Al[0]);
        split_pack(b0[er + 8], b1[er + 8], Ah[1], Al[1]);
        split_pack(b8[er],     b9[er],     Ah[2], Al[2]);
        split_pack(b8[er + 8], b9[er + 8], Ah[3], Al[3]);

#pragma unroll
        for (int nt = 0; nt < 8; ++nt) {
            const uint4 bb = __ldg(gB + (kt * 8 + nt) * 32 + lane);
            mma_bf16(acc[nt], Ah, bb.x, bb.y);
            mma_bf16(acc[nt], Al, bb.x, bb.y);
            mma_bf16(acc[nt], Ah, bb.z, bb.w);
        }
    }

#pragma unroll
    for (int nt = 0; nt < 8; ++nt) {
        const int c0 = nt * 8 + 2 * t;
        sOut[(c0)     * HT + er]     = silu_f(acc[nt][0]);
        sOut[(c0 + 1) * HT + er]     = silu_f(acc[nt][1]);
        sOut[(c0)     * HT + er + 8] = silu_f(acc[nt][2]);
        sOut[(c0 + 1) * HT + er + 8] = silu_f(acc[nt][3]);
    }
}

// ---------------------------------------------------------------------------
// Kernel 1: MLP. Layer 1 scalar; layers 2-3 HMMA; -> split bf16 A-fragments.
// ---------------------------------------------------------------------------
__global__ void __launch_bounds__(256, 2)
mlp_kernel(const float* __restrict__ emb, const float* __restrict__ Wm1)
{
    extern __shared__ float sm[];
    float* sE  = sm;
    float* sW1 = sm + 1024;
    float* sHa = sm + 1536;
    float* sHb = sm + 1536 + HH * HT;

    const int tid = threadIdx.x;
    const size_t e0 = (size_t)blockIdx.x * 128;

    for (int i = tid; i < 1024; i += 256) sE[i] = emb[e0 * 8 + i];
    for (int i = tid; i < 512; i += 256)  sW1[i] = Wm1[i];
    __syncthreads();

    const int jq = tid & 15;
    const int eg = tid >> 4;
    const int jbase = jq * 4;
    const int ebase = eg * 8;

    // layer 1 (scalar, K=8)
    {
        float wv[8][4];
#pragma unroll
        for (int r = 0; r < 8; ++r) {
            const float4 w4 = *(const float4*)(sW1 + r * HH + jbase);
            wv[r][0] = w4.x; wv[r][1] = w4.y; wv[r][2] = w4.z; wv[r][3] = w4.w;
        }
#pragma unroll
        for (int e = 0; e < 8; ++e) {
            const float4 ea = *(const float4*)(sE + (ebase + e) * 8);
            const float4 eb = *(const float4*)(sE + (ebase + e) * 8 + 4);
            const float er8[8] = {ea.x, ea.y, ea.z, ea.w, eb.x, eb.y, eb.z, eb.w};
#pragma unroll
            for (int c = 0; c < 4; ++c) {
                float acc = 0.f;
#pragma unroll
                for (int r = 0; r < 8; ++r) acc += er8[r] * wv[r][c];
                sHa[(jbase + c) * HT + ebase + e] = silu_f(acc);
            }
        }
    }
    __syncthreads();

    const int w    = tid >> 5;
    const int lane = tid & 31;

    layer_hmma(g_b23,        sHa, sHb, w, lane);   // layer 2
    __syncthreads();
    layer_hmma(g_b23 + 1024, sHb, sHa, w, lane);   // layer 3
    __syncthreads();

    // build + store A fragments (bf16 hi/lo) in m16n8k16 order
    const int g = lane >> 2, t = lane & 3;
    const int er = w * 16 + g;

#pragma unroll
    for (int kt = 0; kt < 4; ++kt) {
        const int k0 = kt * 16 + 2 * t;
        const float* b0 = sHa + (k0)     * HT;
        const float* b1 = sHa + (k0 + 1) * HT;
        const float* b8 = sHa + (k0 + 8) * HT;
        const float* b9 = sHa + (k0 + 9) * HT;
        uint4 vh, vl;
        split_pack(b0[er],     b1[er],     vh.x, vl.x);
        split_pack(b0[er + 8], b1[er + 8], vh.y, vl.y);
        split_pack(b8[er],     b9[er],     vh.z, vl.z);
        split_pack(b8[er + 8], b9[er + 8], vh.w, vl.w);
        const int idx = ((blockIdx.x * 8 + w) * 4 + kt) * 32 + lane;
        g_ah4[idx] = vh;
        g_al4[idx] = vl;
    }
}

// ---------------------------------------------------------------------------
// Kernel 2: zero agg
// ---------------------------------------------------------------------------
__global__ void __launch_bounds__(256)
zero_kernel()
{
    const size_t i = (size_t)blockIdx.x * 256 + threadIdx.x;
    ((float4*)g_agg)[i] = make_float4(0.f, 0.f, 0.f, 0.f);
}

// ---------------------------------------------------------------------------
// Kernel 3: FUSED GEMM4 + messages + interleaved scatter (best: 259us).
// ---------------------------------------------------------------------------
__global__ void __launch_bounds__(256, 2)
fused_kernel(const float* __restrict__ nf, const float* __restrict__ ef,
             const float* __restrict__ attrs,
             const int* __restrict__ snd, const int* __restrict__ rcv)
{
    __shared__ int    s_snd[8][16];
    __shared__ int    s_rcv[8][16];
    __shared__ float4 s_y[8][32 * 5];

    const int tid  = threadIdx.x;
    const int w    = tid >> 5;
    const int lane = tid & 31;
    const int gr   = lane >> 2;
    const int t    = lane & 3;
    const size_t e0 = (size_t)blockIdx.x * 128;

    if (lane < 16) {
        s_snd[w][lane] = snd[e0 + (size_t)(w * 16 + lane)];
        s_rcv[w][lane] = rcv[e0 + (size_t)(w * 16 + lane)];
    }
    __syncwarp();

    const int eml = gr + 8 * (t & 1);
    const size_t em = e0 + (size_t)(w * 16 + eml);
    const float4 sh = *(const float4*)(attrs + em * 4);
    const float sh0 = sh.x, s1x = sh.y, s1y = sh.z, s1z = sh.w;
    float* pagg = g_agg + (size_t)s_rcv[w][eml] * DD;

    const int jP = lane & 7;
    const int ch4P  = (jP < 2) ? jP : (jP - 2) / 3;
    const int slotP = (jP < 2) ? 0 : ((jP - 2) % 3) + 1;
    const int offMul = (jP < 2) ? 8 : 24;
    const int offAdd = (jP < 2) ? jP * 4 : CC + (jP - 2) * 4;
    const int elBase = lane >> 3;

    uint32_t Ah[4][4], Al[4][4];
#pragma unroll
    for (int kt = 0; kt < 4; ++kt) {
        const int idx = ((blockIdx.x * 8 + w) * 4 + kt) * 32 + lane;
        const uint4 vh = g_ah4[idx];
        const uint4 vl = g_al4[idx];
        Ah[kt][0] = vh.x; Ah[kt][1] = vh.y; Ah[kt][2] = vh.z; Ah[kt][3] = vh.w;
        Al[kt][0] = vl.x; Al[kt][1] = vl.y; Al[kt][2] = vl.z; Al[kt][3] = vl.w;
    }

#pragma unroll 1
    for (int tile = 0; tile < 16; ++tile) {
        const int off = tile * offMul + offAdd;
        float4 xa[4], xb[4], xc[4];
#pragma unroll
        for (int it = 0; it < 4; ++it) {
            const int el = it * 4 + elBase;
            xa[it] = __ldg((const float4*)(nf + (size_t)s_snd[w][el] * DD + off));
            xb[it] = __ldg((const float4*)(nf + (size_t)s_rcv[w][el] * DD + off));
            xc[it] = __ldg((const float4*)(ef + (e0 + (size_t)(w * 16 + el)) * DD + off));
        }

        float acc[5][4];
#pragma unroll
        for (int q = 0; q < 5; ++q)
#pragma unroll
            for (int i = 0; i < 4; ++i) acc[q][i] = 0.f;

#pragma unroll
        for (int q = 0; q < 5; ++q) {
#pragma unroll
            for (int kt = 0; kt < 4; ++kt) {
                const uint4 bb = __ldg(g_b4 + ((kt * 80 + q * 16 + tile) * 32 + lane));
                mma_bf16(acc[q], Ah[kt], bb.x, bb.y);
                mma_bf16(acc[q], Al[kt], bb.x, bb.y);
                mma_bf16(acc[q], Ah[kt], bb.z, bb.w);
            }
        }

#pragma unroll
        for (int it = 0; it < 4; ++it) {
            const int el = it * 4 + elBase;
            const int c = (el & 7) * 4 + (el >> 3) + 2 * ch4P;
            s_y[w][c * 5 + slotP] = make_float4(
                xa[it].x + xb[it].x + xc[it].x,
                xa[it].y + xb[it].y + xc[it].y,
                xa[it].z + xb[it].z + xc[it].z,
                xa[it].w + xb[it].w + xc[it].w);
        }
        __syncwarp();

        const float4* my = &s_y[w][lane * 5];
        const float4 X0 = my[0];
        const float4 V0 = my[1];
        const float4 V1 = my[2];
        const float4 V2 = my[3];
        const float x0[4]  = {X0.x, X0.y, X0.z, X0.w};
        const float xv[12] = {V0.x, V0.y, V0.z, V0.w,
                              V1.x, V1.y, V1.z, V1.w,
                              V2.x, V2.y, V2.z, V2.w};

#pragma unroll
        for (int q = 0; q < 5; ++q) {
            const float s0 = (t & 1) ? acc[q][0] : acc[q][2];
            const float s1 = (t & 1) ? acc[q][1] : acc[q][3];
            const float r0 = __shfl_xor_sync(0xffffffffu, s0, 1);
            const float r1 = __shfl_xor_sync(0xffffffffu, s1, 1);
            if (t & 1) { acc[q][0] = r0; acc[q][1] = r1; }
            else       { acc[q][2] = r0; acc[q][3] = r1; }
        }
        const int cm = tile * 8 + (t >> 1) * 4;

#pragma unroll
        for (int j = 0; j < 4; ++j) {
            const float u0 = xv[3 * j], u1 = xv[3 * j + 1], u2 = xv[3 * j + 2];
            const float dot = u0 * s1x + u1 * s1y + u2 * s1z;
            const float m0 = acc[0][j] * x0[j] * sh0 + acc[1][j] * dot * INV_SQRT3;
            const float cx = u1 * s1z - u2 * s1y;
            const float cy = u2 * s1x - u0 * s1z;
            const float cz = u0 * s1y - u1 * s1x;
            const float mx = acc[2][j] * u0 * sh0 + acc[3][j] * x0[j] * s1x + acc[4][j] * cx * INV_SQRT2;
            const float my2 = acc[2][j] * u1 * sh0 + acc[3][j] * x0[j] * s1y + acc[4][j] * cy * INV_SQRT2;
            const float mz = acc[2][j] * u2 * sh0 + acc[3][j] * x0[j] * s1z + acc[4][j] * cz * INV_SQRT2;
            asm volatile("red.global.add.v4.f32 [%0], {%1,%2,%3,%4};"
                         :: "l"(pagg + (size_t)(cm + j) * 4),
                            "f"(m0), "f"(mx), "f"(my2), "f"(mz)
                         : "memory");
        }
        __syncwarp();
    }
}

// ---------------------------------------------------------------------------
// Kernel 4: out via tensor cores (measured good). Grid (157, 4).
// ---------------------------------------------------------------------------
#define XST 260
#define OUT_SMEM (64 * XST * 4)       // 66560 B

__global__ void __launch_bounds__(256)
out_tc_kernel(const float* __restrict__ nf, float* __restrict__ out)
{
    extern __shared__ float Xs[];

    const int tid = threadIdx.x;
    const int p = blockIdx.y;
    const size_t n0 = (size_t)blockIdx.x * 64;

    for (int i = tid; i < 64 * CC; i += 256) {
        const int n = i >> 7;
        const int c = i & 127;
        float v = 0.f;
        if (n0 + n < NN) v = g_agg[(n0 + n) * DD + c * 4 + p];
        Xs[n * XST + c] = v;
    }
    for (int i = tid; i < 64 * CC; i += 256) {
        const int n = i >> 7;
        const int c = i & 127;
        float v = 0.f;
        if (n0 + n < NN) {
            const int col = (p == 0) ? c : (CC + 3 * c + (p - 1));
            v = nf[(n0 + n) * DD + col];
        }
        Xs[n * XST + 128 + c] = v;
    }
    __syncthreads();

    const int w    = tid >> 5;
    const int lane = tid & 31;
    const int mg   = w & 3;
    const int nh   = w >> 2;
    const int g = lane >> 2, t = lane & 3;
    const int rA = mg * 16 + g;
    const int s = (p == 0) ? 0 : 1;

    float acc[8][4];
#pragma unroll
    for (int nt8 = 0; nt8 < 8; ++nt8)
#pragma unroll
        for (int i = 0; i < 4; ++i) acc[nt8][i] = 0.f;

#pragma unroll 1
    for (int kt = 0; kt < 16; ++kt) {
        const int k = kt * 16 + 2 * t;
        const float* r0 = Xs + rA * XST;
        const float* r8 = Xs + (rA + 8) * XST;
        uint32_t Ah[4], Al[4];
        split_pack(r0[k],     r0[k + 1], Ah[0], Al[0]);
        split_pack(r8[k],     r8[k + 1], Ah[1], Al[1]);
        split_pack(r0[k + 8], r0[k + 9], Ah[2], Al[2]);
        split_pack(r8[k + 8], r8[k + 9], Ah[3], Al[3]);

#pragma unroll
        for (int nt8 = 0; nt8 < 8; ++nt8) {
            const int nt = nh * 8 + nt8;
            const uint4 bb = __ldg(g_ob4 + ((s * 16 + kt) * 16 + nt) * 32 + lane);
            mma_bf16(acc[nt8], Ah, bb.x, bb.y);
            mma_bf16(acc[nt8], Al, bb.x, bb.y);
            mma_bf16(acc[nt8], Ah, bb.z, bb.w);
        }
    }

#pragma unroll
    for (int nt8 = 0; nt8 < 8; ++nt8) {
        const int d0 = nh * 64 + nt8 * 8 + 2 * t;
#pragma unroll
        for (int half = 0; half < 2; ++half) {
            const int r = rA + half * 8;
            if (n0 + r >= NN) continue;
            const float v0 = Xs[r * XST + d0]     + acc[nt8][half * 2]     * LIN_SCALE;
            const float v1 = Xs[r * XST + d0 + 1] + acc[nt8][half * 2 + 1] * LIN_SCALE;
            float* ob = out + (n0 + r) * DD;
            if (p == 0) {
                *(float2*)(ob + d0) = make_float2(v0, v1);
            } else {
                ob[CC + 3 * d0 + (p - 1)]       = v0;
                ob[CC + 3 * (d0 + 1) + (p - 1)] = v1;
            }
        }
    }
}

// ---------------------------------------------------------------------------
extern "C" void kernel_launch(void* const* d_in, const int* in_sizes, int n_in,
                              void* d_out, int out_size)
{
    const float* nf    = (const float*)d_in[0];
    const float* ef    = (const float*)d_in[1];
    const float* attrs = (const float*)d_in[2];
    const float* emb   = (const float*)d_in[3];
    const int*   snd   = (const int*)d_in[4];
    const int*   rcv   = (const int*)d_in[5];
    const float* Wm1   = (const float*)d_in[6];
    const float* Wm2   = (const float*)d_in[7];
    const float* Wm3   = (const float*)d_in[8];
    const float* Wm4   = (const float*)d_in[9];
    const float* rW0   = (const float*)d_in[10];
    const float* rW1   = (const float*)d_in[11];
    const float* sW0   = (const float*)d_in[12];
    const float* sW1   = (const float*)d_in[13];
    float* out = (float*)d_out;

    const int mlp_smem = (1536 + 2 * HH * HT) * 4;   // 72704 B
    static bool attr_done = false;
    if (!attr_done) {
        cudaFuncSetAttribute(mlp_kernel, cudaFuncAttributeMaxDynamicSharedMemorySize, mlp_smem);
        cudaFuncSetAttribute(out_tc_kernel, cudaFuncAttributeMaxDynamicSharedMemorySize, OUT_SMEM);
        attr_done = true;
    }

    zero_kernel<<<(NN * DD) / (256 * 4), 256>>>();
    prep_b4_kernel<<<(4 * 80 * 32 + 255) / 256, 256>>>(Wm4);
    prep_b23_kernel<<<(2 * 4 * 8 * 32 + 255) / 256, 256>>>(Wm2, Wm3);
    prep_ow_kernel<<<(2 * 16 * 16 * 32 + 255) / 256, 256>>>(rW0, rW1, sW0, sW1);
    mlp_kernel<<<EE / 128, 256, mlp_smem>>>(emb, Wm1);
    fused_kernel<<<EE / 128, 256>>>(nf, ef, attrs, snd, rcv);
    out_tc_kernel<<<dim3((NN + 63) / 64, 4), 256, OUT_SMEM>>>(nf, out);
}